// round 1
// baseline (speedup 1.0000x reference)
#include <cuda_runtime.h>
#include <cstdint>

#define H 512
#define TOT (16*256*256)
#define HALF (TOT/2)
#define SCALE_INV 0.1f
#define STRENGTH 5.0f

typedef unsigned long long u64;

// ---------- packed f32x2 helpers ----------
__device__ __forceinline__ u64 pk(float lo, float hi) {
    u64 r; asm("mov.b64 %0, {%1, %2};" : "=l"(r) : "f"(lo), "f"(hi)); return r;
}
__device__ __forceinline__ void upk(u64 v, float& lo, float& hi) {
    asm("mov.b64 {%0, %1}, %2;" : "=f"(lo), "=f"(hi) : "l"(v));
}
__device__ __forceinline__ u64 fma2(u64 a, u64 b, u64 c) {
    u64 d; asm("fma.rn.f32x2 %0, %1, %2, %3;" : "=l"(d) : "l"(a), "l"(b), "l"(c)); return d;
}
__device__ __forceinline__ u64 cos2(u64 v) {
    float lo, hi; upk(v, lo, hi);
    return pk(__cosf(lo), __cosf(hi));
}

// ---------- prelude results ----------
__device__ float g_A[4];      // expm(gen)
__device__ float g_bns[32];   // gamma * rsqrt(var+eps)
__device__ float g_bno[32];   // beta - mean * scale

__global__ void prelude_kernel(const float* __restrict__ gen,
                               const float* __restrict__ gam,
                               const float* __restrict__ bet,
                               const float* __restrict__ mean,
                               const float* __restrict__ var) {
    int t = threadIdx.x;
    if (t == 0) {
        double m0 = gen[0], m1 = gen[1], m2 = gen[2], m3 = gen[3];
        double a0 = 1.0, a1 = 0.0, a2 = 0.0, a3 = 1.0;      // accumulator = I
        double t0 = 1.0, t1 = 0.0, t2 = 0.0, t3 = 1.0;      // term = I
        for (int k = 1; k <= 18; k++) {
            double n0 = (t0 * m0 + t1 * m2) / k;
            double n1 = (t0 * m1 + t1 * m3) / k;
            double n2 = (t2 * m0 + t3 * m2) / k;
            double n3 = (t2 * m1 + t3 * m3) / k;
            t0 = n0; t1 = n1; t2 = n2; t3 = n3;
            a0 += n0; a1 += n1; a2 += n2; a3 += n3;
        }
        g_A[0] = (float)a0; g_A[1] = (float)a1;
        g_A[2] = (float)a2; g_A[3] = (float)a3;
    }
    if (t < 32) {
        float s = gam[t] * rsqrtf(var[t] + 0.001f);
        g_bns[t] = s;
        g_bno[t] = bet[t] - mean[t] * s;
    }
}

// ---------- bilinear sample ----------
__device__ __forceinline__ float bil(const float* __restrict__ img, float r, float c) {
    r = fminf(fmaxf(r, 0.0f), (float)(H - 1));
    c = fminf(fmaxf(c, 0.0f), (float)(H - 1));
    float rf = floorf(r), cf = floorf(c);
    int r0 = (int)rf, c0 = (int)cf;
    int r1 = min(r0 + 1, H - 1), c1 = min(c0 + 1, H - 1);
    float wr = r - rf, wc = c - cf;
    float v00 = __ldg(img + r0 * H + c0);
    float v01 = __ldg(img + r0 * H + c1);
    float v10 = __ldg(img + r1 * H + c0);
    float v11 = __ldg(img + r1 * H + c1);
    float top = v00 + wc * (v01 - v00);
    float bot = v10 + wc * (v11 - v10);
    return top + wr * (bot - top);
}

// ---------- main kernel: 2 pixels / thread, f32x2 math ----------
__global__ __launch_bounds__(256)
void rmodel_kernel(const float* __restrict__ x,
                   const float* __restrict__ trans,
                   const float* __restrict__ w0, const float* __restrict__ b0,
                   const float* __restrict__ w1, const float* __restrict__ b1,
                   const float* __restrict__ w2, const float* __restrict__ b2,
                   const float* __restrict__ wf,
                   const float* __restrict__ img,
                   float* __restrict__ out) {
    // shared: duplicated {w,w} pairs so one LDS.64 feeds one FFMA2
    __shared__ u64 s_w0[64];        // [c*32+j]
    __shared__ u64 s_b0[32];
    __shared__ u64 s_w1[1024];      // [k*32+j]
    __shared__ u64 s_b1[32];
    __shared__ u64 s_w2[1024];
    __shared__ u64 s_b2[32];
    __shared__ u64 s_bns[32], s_bno[32];
    __shared__ u64 s_wf[64];        // [k*2+m]

    int tid = threadIdx.x;
    for (int i = tid; i < 1024; i += 256) {
        float a = w1[i]; s_w1[i] = pk(a, a);
        float b = w2[i]; s_w2[i] = pk(b, b);
    }
    if (tid < 64) { float a = w0[tid]; s_w0[tid] = pk(a, a);
                    float b = wf[tid]; s_wf[tid] = pk(b, b); }
    if (tid < 32) {
        float a = b0[tid]; s_b0[tid] = pk(a, a);
        float b = b1[tid]; s_b1[tid] = pk(b, b);
        float c = b2[tid]; s_b2[tid] = pk(c, c);
        float s = g_bns[tid]; s_bns[tid] = pk(s, s);
        float o = g_bno[tid]; s_bno[tid] = pk(o, o);
    }
    __syncthreads();

    int i = blockIdx.x * 256 + tid;           // pixel pair: (i, i+HALF)
    int ib = i + HALF;

    float xa0 = __ldg(x + 3 * i),  xa1 = __ldg(x + 3 * i + 1);
    float xb0 = __ldg(x + 3 * ib), xb1 = __ldg(x + 3 * ib + 1);

    float A0 = g_A[0], A1 = g_A[1], A2 = g_A[2], A3 = g_A[3];
    float t0 = __ldg(trans), t1 = __ldg(trans + 1);

    // c = A x + t
    float ca0 = fmaf(A0, xa0, fmaf(A1, xa1, t0));
    float ca1 = fmaf(A2, xa0, fmaf(A3, xa1, t1));
    float cb0 = fmaf(A0, xb0, fmaf(A1, xb1, t0));
    float cb1 = fmaf(A2, xb0, fmaf(A3, xb1, t1));

    u64 c0 = pk(ca0, cb0);
    u64 c1 = pk(ca1, cb1);
    u64 yc0 = pk(ca0 * SCALE_INV, cb0 * SCALE_INV);
    u64 yc1 = pk(ca1 * SCALE_INV, cb1 * SCALE_INV);

    u64 y[32];
    u64 z[32];

    // layer 0: 2 -> 32
    #pragma unroll
    for (int j = 0; j < 32; j++) {
        u64 acc = fma2(yc0, s_w0[j], fma2(yc1, s_w0[32 + j], s_b0[j]));
        y[j] = cos2(acc);
    }

    // layer 1: 32 -> 32
    #pragma unroll 4
    for (int j = 0; j < 32; j++) {
        u64 acc = s_b1[j];
        #pragma unroll
        for (int k = 0; k < 32; k++) acc = fma2(y[k], s_w1[k * 32 + j], acc);
        z[j] = cos2(acc);
    }

    // layer 2: 32 -> 32, then BN + cos
    #pragma unroll 4
    for (int j = 0; j < 32; j++) {
        u64 acc = s_b2[j];
        #pragma unroll
        for (int k = 0; k < 32; k++) acc = fma2(z[k], s_w2[k * 32 + j], acc);
        u64 y2 = cos2(acc);
        y[j] = cos2(fma2(y2, s_bns[j], s_bno[j]));
    }

    // final projection 32 -> 2, c += 5*d
    u64 d0 = 0ull, d1 = 0ull;
    #pragma unroll
    for (int k = 0; k < 32; k++) {
        d0 = fma2(y[k], s_wf[2 * k], d0);
        d1 = fma2(y[k], s_wf[2 * k + 1], d1);
    }
    u64 five = pk(STRENGTH, STRENGTH);
    c0 = fma2(five, d0, c0);
    c1 = fma2(five, d1, c1);

    float ra, rb, cca, ccb;
    upk(c0, ra, rb);
    upk(c1, cca, ccb);

    out[i]  = bil(img, ra, cca);
    out[ib] = bil(img, rb, ccb);
}

extern "C" void kernel_launch(void* const* d_in, const int* in_sizes, int n_in,
                              void* d_out, int out_size) {
    const float* x      = (const float*)d_in[0];
    const float* gen    = (const float*)d_in[1];
    const float* trans  = (const float*)d_in[2];
    const float* w0     = (const float*)d_in[3];
    const float* b0     = (const float*)d_in[4];
    const float* w1     = (const float*)d_in[5];
    const float* b1     = (const float*)d_in[6];
    const float* w2     = (const float*)d_in[7];
    const float* b2     = (const float*)d_in[8];
    const float* gam    = (const float*)d_in[9];
    const float* bet    = (const float*)d_in[10];
    const float* mean   = (const float*)d_in[11];
    const float* var    = (const float*)d_in[12];
    const float* wf     = (const float*)d_in[13];
    const float* img    = (const float*)d_in[14];
    float* out = (float*)d_out;

    prelude_kernel<<<1, 32>>>(gen, gam, bet, mean, var);
    rmodel_kernel<<<HALF / 256, 256>>>(x, trans, w0, b0, w1, b1, w2, b2,
                                       wf, img, out);
}

// round 3
// speedup vs baseline: 1.1774x; 1.1774x over previous
#include <cuda_runtime.h>
#include <cstdint>

#define H 512
#define TOT (16*256*256)
#define HALF (TOT/2)
#define SCALE_INV 0.1f
#define STRENGTH 5.0f

typedef unsigned long long u64;

// ---------- packed f32x2 helpers ----------
__device__ __forceinline__ u64 pk(float lo, float hi) {
    u64 r; asm("mov.b64 %0, {%1, %2};" : "=l"(r) : "f"(lo), "f"(hi)); return r;
}
__device__ __forceinline__ void upk(u64 v, float& lo, float& hi) {
    asm("mov.b64 {%0, %1}, %2;" : "=f"(lo), "=f"(hi) : "l"(v));
}
__device__ __forceinline__ u64 fma2(u64 a, u64 b, u64 c) {
    u64 d; asm("fma.rn.f32x2 %0, %1, %2, %3;" : "=l"(d) : "l"(a), "l"(b), "l"(c)); return d;
}
__device__ __forceinline__ u64 cos2(u64 v) {
    float lo, hi; upk(v, lo, hi);
    return pk(__cosf(lo), __cosf(hi));
}

// ---------- prelude results ----------
__device__ float g_A[4];      // expm(gen)
__device__ float g_bns[32];   // gamma * rsqrt(var+eps)
__device__ float g_bno[32];   // beta - mean * scale

__global__ void prelude_kernel(const float* __restrict__ gen,
                               const float* __restrict__ gam,
                               const float* __restrict__ bet,
                               const float* __restrict__ mean,
                               const float* __restrict__ var) {
    int t = threadIdx.x;
    if (t == 0) {
        double m0 = gen[0], m1 = gen[1], m2 = gen[2], m3 = gen[3];
        double a0 = 1.0, a1 = 0.0, a2 = 0.0, a3 = 1.0;      // accumulator = I
        double t0 = 1.0, t1 = 0.0, t2 = 0.0, t3 = 1.0;      // term = I
        for (int k = 1; k <= 18; k++) {
            double n0 = (t0 * m0 + t1 * m2) / k;
            double n1 = (t0 * m1 + t1 * m3) / k;
            double n2 = (t2 * m0 + t3 * m2) / k;
            double n3 = (t2 * m1 + t3 * m3) / k;
            t0 = n0; t1 = n1; t2 = n2; t3 = n3;
            a0 += n0; a1 += n1; a2 += n2; a3 += n3;
        }
        g_A[0] = (float)a0; g_A[1] = (float)a1;
        g_A[2] = (float)a2; g_A[3] = (float)a3;
    }
    if (t < 32) {
        float s = gam[t] * rsqrtf(var[t] + 0.001f);
        g_bns[t] = s;
        g_bno[t] = bet[t] - mean[t] * s;
    }
}

// ---------- bilinear sample ----------
__device__ __forceinline__ float bil(const float* __restrict__ img, float r, float c) {
    r = fminf(fmaxf(r, 0.0f), (float)(H - 1));
    c = fminf(fmaxf(c, 0.0f), (float)(H - 1));
    float rf = floorf(r), cf = floorf(c);
    int r0 = (int)rf, c0 = (int)cf;
    int r1 = min(r0 + 1, H - 1), c1 = min(c0 + 1, H - 1);
    float wr = r - rf, wc = c - cf;
    float v00 = __ldg(img + r0 * H + c0);
    float v01 = __ldg(img + r0 * H + c1);
    float v10 = __ldg(img + r1 * H + c0);
    float v11 = __ldg(img + r1 * H + c1);
    float top = v00 + wc * (v01 - v00);
    float bot = v10 + wc * (v11 - v10);
    return top + wr * (bot - top);
}

// ---------- main kernel: 2 pixels / thread, f32x2 + LDS.128 dual-column ----------
#define BLK 128
__global__ __launch_bounds__(BLK)
void rmodel_kernel(const float* __restrict__ x,
                   const float* __restrict__ trans,
                   const float* __restrict__ w0, const float* __restrict__ b0,
                   const float* __restrict__ w1, const float* __restrict__ b1,
                   const float* __restrict__ w2, const float* __restrict__ b2,
                   const float* __restrict__ wf,
                   const float* __restrict__ img,
                   float* __restrict__ out) {
    // s_w[k][jh] = {w[k][2jh] dup, w[k][2jh+1] dup} -> one LDS.128 feeds 2 FFMA2
    __shared__ ulonglong2 s_w1[32 * 16];
    __shared__ ulonglong2 s_w2[32 * 16];
    __shared__ u64 s_w0[64];        // [c*32+j] duplicated
    __shared__ u64 s_b0[32], s_b1[32], s_b2[32];
    __shared__ u64 s_bns[32], s_bno[32];
    __shared__ u64 s_wf[64];        // [k*2+m] duplicated

    int tid = threadIdx.x;
    for (int e = tid; e < 512; e += BLK) {
        int k = e >> 4, jh = e & 15;
        float a0 = w1[k * 32 + 2 * jh], a1 = w1[k * 32 + 2 * jh + 1];
        s_w1[e] = make_ulonglong2(pk(a0, a0), pk(a1, a1));
        float c0 = w2[k * 32 + 2 * jh], c1 = w2[k * 32 + 2 * jh + 1];
        s_w2[e] = make_ulonglong2(pk(c0, c0), pk(c1, c1));
    }
    if (tid < 64) { float a = w0[tid]; s_w0[tid] = pk(a, a);
                    float b = wf[tid]; s_wf[tid] = pk(b, b); }
    if (tid < 32) {
        float a = b0[tid]; s_b0[tid] = pk(a, a);
        float b = b1[tid]; s_b1[tid] = pk(b, b);
        float c = b2[tid]; s_b2[tid] = pk(c, c);
        float s = g_bns[tid]; s_bns[tid] = pk(s, s);
        float o = g_bno[tid]; s_bno[tid] = pk(o, o);
    }
    __syncthreads();

    int i = blockIdx.x * BLK + tid;           // pixel pair: (i, i+HALF)
    int ib = i + HALF;

    float xa0 = __ldg(x + 3 * i),  xa1 = __ldg(x + 3 * i + 1);
    float xb0 = __ldg(x + 3 * ib), xb1 = __ldg(x + 3 * ib + 1);

    float A0 = g_A[0], A1 = g_A[1], A2 = g_A[2], A3 = g_A[3];
    float t0 = __ldg(trans), t1 = __ldg(trans + 1);

    // c = A x + t
    float ca0 = fmaf(A0, xa0, fmaf(A1, xa1, t0));
    float ca1 = fmaf(A2, xa0, fmaf(A3, xa1, t1));
    float cb0 = fmaf(A0, xb0, fmaf(A1, xb1, t0));
    float cb1 = fmaf(A2, xb0, fmaf(A3, xb1, t1));

    u64 c0 = pk(ca0, cb0);
    u64 c1 = pk(ca1, cb1);
    u64 yc0 = pk(ca0 * SCALE_INV, cb0 * SCALE_INV);
    u64 yc1 = pk(ca1 * SCALE_INV, cb1 * SCALE_INV);

    u64 y[32];
    u64 z[32];

    // layer 0: 2 -> 32
    #pragma unroll
    for (int j = 0; j < 32; j++) {
        u64 acc = fma2(yc0, s_w0[j], fma2(yc1, s_w0[32 + j], s_b0[j]));
        y[j] = cos2(acc);
    }

    // layer 1: 32 -> 32  (dual-column accumulators, LDS.128)
    #pragma unroll
    for (int jh = 0; jh < 16; jh++) {
        u64 a0 = s_b1[2 * jh], a1 = s_b1[2 * jh + 1];
        #pragma unroll
        for (int k = 0; k < 32; k++) {
            ulonglong2 w = s_w1[k * 16 + jh];
            a0 = fma2(y[k], w.x, a0);
            a1 = fma2(y[k], w.y, a1);
        }
        z[2 * jh]     = cos2(a0);
        z[2 * jh + 1] = cos2(a1);
    }

    // layer 2: 32 -> 32, fused BN + cos
    #pragma unroll
    for (int jh = 0; jh < 16; jh++) {
        u64 a0 = s_b2[2 * jh], a1 = s_b2[2 * jh + 1];
        #pragma unroll
        for (int k = 0; k < 32; k++) {
            ulonglong2 w = s_w2[k * 16 + jh];
            a0 = fma2(z[k], w.x, a0);
            a1 = fma2(z[k], w.y, a1);
        }
        u64 p0 = cos2(a0);
        u64 p1 = cos2(a1);
        y[2 * jh]     = cos2(fma2(p0, s_bns[2 * jh],     s_bno[2 * jh]));
        y[2 * jh + 1] = cos2(fma2(p1, s_bns[2 * jh + 1], s_bno[2 * jh + 1]));
    }

    // final projection 32 -> 2, c += 5*d
    u64 d0 = 0ull, d1 = 0ull;
    #pragma unroll
    for (int k = 0; k < 32; k++) {
        d0 = fma2(y[k], s_wf[2 * k], d0);
        d1 = fma2(y[k], s_wf[2 * k + 1], d1);
    }
    u64 five = pk(STRENGTH, STRENGTH);
    c0 = fma2(five, d0, c0);
    c1 = fma2(five, d1, c1);

    float ra, rb, cca, ccb;
    upk(c0, ra, rb);
    upk(c1, cca, ccb);

    out[i]  = bil(img, ra, cca);
    out[ib] = bil(img, rb, ccb);
}

extern "C" void kernel_launch(void* const* d_in, const int* in_sizes, int n_in,
                              void* d_out, int out_size) {
    const float* x      = (const float*)d_in[0];
    const float* gen    = (const float*)d_in[1];
    const float* trans  = (const float*)d_in[2];
    const float* w0     = (const float*)d_in[3];
    const float* b0     = (const float*)d_in[4];
    const float* w1     = (const float*)d_in[5];
    const float* b1     = (const float*)d_in[6];
    const float* w2     = (const float*)d_in[7];
    const float* b2     = (const float*)d_in[8];
    const float* gam    = (const float*)d_in[9];
    const float* bet    = (const float*)d_in[10];
    const float* mean   = (const float*)d_in[11];
    const float* var    = (const float*)d_in[12];
    const float* wf     = (const float*)d_in[13];
    const float* img    = (const float*)d_in[14];
    float* out = (float*)d_out;

    prelude_kernel<<<1, 32>>>(gen, gam, bet, mean, var);
    rmodel_kernel<<<HALF / BLK, BLK>>>(x, trans, w0, b0, w1, b1, w2, b2,
                                       wf, img, out);
}

// round 4
// speedup vs baseline: 1.4429x; 1.2255x over previous
#include <cuda_runtime.h>
#include <cstdint>

#define H 512
#define TOT (16*256*256)
#define HALF (TOT/2)
#define SCALE_INV 0.1f
#define STRENGTH 5.0f

typedef unsigned long long u64;

// ---------- packed f32x2 helpers ----------
__device__ __forceinline__ u64 pk(float lo, float hi) {
    u64 r; asm("mov.b64 %0, {%1, %2};" : "=l"(r) : "f"(lo), "f"(hi)); return r;
}
__device__ __forceinline__ void upk(u64 v, float& lo, float& hi) {
    asm("mov.b64 {%0, %1}, %2;" : "=f"(lo), "=f"(hi) : "l"(v));
}
__device__ __forceinline__ u64 fma2(u64 a, u64 b, u64 c) {
    u64 d; asm("fma.rn.f32x2 %0, %1, %2, %3;" : "=l"(d) : "l"(a), "l"(b), "l"(c)); return d;
}
__device__ __forceinline__ u64 cos2(u64 v) {
    float lo, hi; upk(v, lo, hi);
    return pk(__cosf(lo), __cosf(hi));
}

// ---------- prelude results ----------
__device__ float g_A[4];                     // expm(gen)
__device__ __align__(8) float g_bns[32];     // gamma * rsqrt(var+eps)
__device__ __align__(8) float g_bno[32];     // beta - mean * scale

__global__ void prelude_kernel(const float* __restrict__ gen,
                               const float* __restrict__ gam,
                               const float* __restrict__ bet,
                               const float* __restrict__ mean,
                               const float* __restrict__ var) {
    int t = threadIdx.x;
    if (t == 0) {
        double m0 = gen[0], m1 = gen[1], m2 = gen[2], m3 = gen[3];
        double a0 = 1.0, a1 = 0.0, a2 = 0.0, a3 = 1.0;
        double t0 = 1.0, t1 = 0.0, t2 = 0.0, t3 = 1.0;
        for (int k = 1; k <= 18; k++) {
            double n0 = (t0 * m0 + t1 * m2) / k;
            double n1 = (t0 * m1 + t1 * m3) / k;
            double n2 = (t2 * m0 + t3 * m2) / k;
            double n3 = (t2 * m1 + t3 * m3) / k;
            t0 = n0; t1 = n1; t2 = n2; t3 = n3;
            a0 += n0; a1 += n1; a2 += n2; a3 += n3;
        }
        g_A[0] = (float)a0; g_A[1] = (float)a1;
        g_A[2] = (float)a2; g_A[3] = (float)a3;
    }
    if (t < 32) {
        float s = gam[t] * rsqrtf(var[t] + 0.001f);
        g_bns[t] = s;
        g_bno[t] = bet[t] - mean[t] * s;
    }
}

// ---------- bilinear sample ----------
__device__ __forceinline__ float bil(const float* __restrict__ img, float r, float c) {
    r = fminf(fmaxf(r, 0.0f), (float)(H - 1));
    c = fminf(fmaxf(c, 0.0f), (float)(H - 1));
    float rf = floorf(r), cf = floorf(c);
    int r0 = (int)rf, c0 = (int)cf;
    int r1 = min(r0 + 1, H - 1), c1 = min(c0 + 1, H - 1);
    float wr = r - rf, wc = c - cf;
    float v00 = __ldg(img + r0 * H + c0);
    float v01 = __ldg(img + r0 * H + c1);
    float v10 = __ldg(img + r1 * H + c0);
    float v11 = __ldg(img + r1 * H + c1);
    float top = v00 + wc * (v01 - v00);
    float bot = v10 + wc * (v11 - v10);
    return top + wr * (bot - top);
}

// ---------- main kernel ----------
// 2 pixels/thread. f32x2 lanes = two adjacent OUTPUT columns of one pixel.
// Weight operand {w[k][2j], w[k][2j+1]} = direct non-dup LDS.64 (1 wavefront).
// Activation dup {y[k],y[k]} built in regs, reused across all 16 column-pairs.
#define BLK 128
__global__ __launch_bounds__(BLK)
void rmodel_kernel(const float* __restrict__ x,
                   const float* __restrict__ trans,
                   const float* __restrict__ w0, const float* __restrict__ b0,
                   const float* __restrict__ w1, const float* __restrict__ b1,
                   const float* __restrict__ w2, const float* __restrict__ b2,
                   const float* __restrict__ wf,
                   const float* __restrict__ img,
                   float* __restrict__ out) {
    __shared__ u64 s_w1[512];   // [k*16+jp] = {w1[k][2jp], w1[k][2jp+1]}
    __shared__ u64 s_w2[512];
    __shared__ u64 s_w0[32];    // [c*16+jp]
    __shared__ u64 s_b0[16], s_b1[16], s_b2[16];
    __shared__ u64 s_bns[16], s_bno[16];
    __shared__ u64 s_wf[32];    // [k] = {wf[k][0], wf[k][1]}

    int tid = threadIdx.x;
    {   // weight rows are contiguous floats -> packed pairs are direct u64 copies
        const u64* gw1 = (const u64*)w1;
        const u64* gw2 = (const u64*)w2;
        for (int e = tid; e < 512; e += BLK) { s_w1[e] = gw1[e]; s_w2[e] = gw2[e]; }
        if (tid < 32) { s_w0[tid] = ((const u64*)w0)[tid];
                        s_wf[tid] = ((const u64*)wf)[tid]; }
        if (tid < 16) {
            s_b0[tid]  = ((const u64*)b0)[tid];
            s_b1[tid]  = ((const u64*)b1)[tid];
            s_b2[tid]  = ((const u64*)b2)[tid];
            s_bns[tid] = pk(g_bns[2 * tid], g_bns[2 * tid + 1]);
            s_bno[tid] = pk(g_bno[2 * tid], g_bno[2 * tid + 1]);
        }
    }
    __syncthreads();

    int i = blockIdx.x * BLK + tid;           // pixels (i, i+HALF)
    int ib = i + HALF;

    float xa0 = __ldg(x + 3 * i),  xa1 = __ldg(x + 3 * i + 1);
    float xb0 = __ldg(x + 3 * ib), xb1 = __ldg(x + 3 * ib + 1);

    float A0 = g_A[0], A1 = g_A[1], A2 = g_A[2], A3 = g_A[3];
    float t0 = __ldg(trans), t1 = __ldg(trans + 1);

    // c = A x + t
    float ca0 = fmaf(A0, xa0, fmaf(A1, xa1, t0));
    float ca1 = fmaf(A2, xa0, fmaf(A3, xa1, t1));
    float cb0 = fmaf(A0, xb0, fmaf(A1, xb1, t0));
    float cb1 = fmaf(A2, xb0, fmaf(A3, xb1, t1));

    u64 accA[16], accB[16];
    float yA[32], yB[32];
    float zA[32], zB[32];

    // ---- layer 0: 2 -> 32 ----
    {
        u64 a0d = pk(ca0 * SCALE_INV, ca0 * SCALE_INV);
        u64 a1d = pk(ca1 * SCALE_INV, ca1 * SCALE_INV);
        u64 b0d = pk(cb0 * SCALE_INV, cb0 * SCALE_INV);
        u64 b1d = pk(cb1 * SCALE_INV, cb1 * SCALE_INV);
        #pragma unroll
        for (int jp = 0; jp < 16; jp++) {
            u64 wa = s_w0[jp], wb = s_w0[16 + jp], bb = s_b0[jp];
            u64 ra = fma2(a0d, wa, fma2(a1d, wb, bb));
            u64 rb = fma2(b0d, wa, fma2(b1d, wb, bb));
            float u, v;
            upk(ra, u, v); yA[2 * jp] = __cosf(u); yA[2 * jp + 1] = __cosf(v);
            upk(rb, u, v); yB[2 * jp] = __cosf(u); yB[2 * jp + 1] = __cosf(v);
        }
    }

    // ---- layer 1: 32 -> 32 ----
    #pragma unroll
    for (int jp = 0; jp < 16; jp++) { accA[jp] = s_b1[jp]; accB[jp] = s_b1[jp]; }
    #pragma unroll
    for (int k = 0; k < 32; k++) {
        u64 da = pk(yA[k], yA[k]);
        u64 db = pk(yB[k], yB[k]);
        #pragma unroll
        for (int jp = 0; jp < 16; jp++) {
            u64 w = s_w1[k * 16 + jp];
            accA[jp] = fma2(da, w, accA[jp]);
            accB[jp] = fma2(db, w, accB[jp]);
        }
    }
    #pragma unroll
    for (int jp = 0; jp < 16; jp++) {
        float u, v;
        upk(accA[jp], u, v); zA[2 * jp] = __cosf(u); zA[2 * jp + 1] = __cosf(v);
        upk(accB[jp], u, v); zB[2 * jp] = __cosf(u); zB[2 * jp + 1] = __cosf(v);
    }

    // ---- layer 2: 32 -> 32, fused BN + cos ----
    #pragma unroll
    for (int jp = 0; jp < 16; jp++) { accA[jp] = s_b2[jp]; accB[jp] = s_b2[jp]; }
    #pragma unroll
    for (int k = 0; k < 32; k++) {
        u64 da = pk(zA[k], zA[k]);
        u64 db = pk(zB[k], zB[k]);
        #pragma unroll
        for (int jp = 0; jp < 16; jp++) {
            u64 w = s_w2[k * 16 + jp];
            accA[jp] = fma2(da, w, accA[jp]);
            accB[jp] = fma2(db, w, accB[jp]);
        }
    }
    #pragma unroll
    for (int jp = 0; jp < 16; jp++) {
        u64 s = s_bns[jp], o = s_bno[jp];
        u64 qa = cos2(fma2(cos2(accA[jp]), s, o));
        u64 qb = cos2(fma2(cos2(accB[jp]), s, o));
        upk(qa, yA[2 * jp], yA[2 * jp + 1]);
        upk(qb, yB[2 * jp], yB[2 * jp + 1]);
    }

    // ---- final 32 -> 2 (packed {d_row, d_col}), c += 5*d ----
    u64 dA = 0ull, dB = 0ull;
    #pragma unroll
    for (int k = 0; k < 32; k++) {
        u64 w = s_wf[k];
        dA = fma2(pk(yA[k], yA[k]), w, dA);
        dB = fma2(pk(yB[k], yB[k]), w, dB);
    }
    u64 five = pk(STRENGTH, STRENGTH);
    u64 cfA = fma2(five, dA, pk(ca0, ca1));
    u64 cfB = fma2(five, dB, pk(cb0, cb1));

    float ra, rca, rb, rcb;
    upk(cfA, ra, rca);
    upk(cfB, rb, rcb);

    out[i]  = bil(img, ra, rca);
    out[ib] = bil(img, rb, rcb);
}

extern "C" void kernel_launch(void* const* d_in, const int* in_sizes, int n_in,
                              void* d_out, int out_size) {
    const float* x      = (const float*)d_in[0];
    const float* gen    = (const float*)d_in[1];
    const float* trans  = (const float*)d_in[2];
    const float* w0     = (const float*)d_in[3];
    const float* b0     = (const float*)d_in[4];
    const float* w1     = (const float*)d_in[5];
    const float* b1     = (const float*)d_in[6];
    const float* w2     = (const float*)d_in[7];
    const float* b2     = (const float*)d_in[8];
    const float* gam    = (const float*)d_in[9];
    const float* bet    = (const float*)d_in[10];
    const float* mean   = (const float*)d_in[11];
    const float* var    = (const float*)d_in[12];
    const float* wf     = (const float*)d_in[13];
    const float* img    = (const float*)d_in[14];
    float* out = (float*)d_out;

    prelude_kernel<<<1, 32>>>(gen, gam, bet, mean, var);
    rmodel_kernel<<<HALF / BLK, BLK>>>(x, trans, w0, b0, w1, b1, w2, b2,
                                       wf, img, out);
}

// round 5
// speedup vs baseline: 1.4700x; 1.0188x over previous
#include <cuda_runtime.h>
#include <cstdint>

#define H 512
#define TOT (16*256*256)
#define HALF (TOT/2)
#define SCALE_INV 0.1f
#define STRENGTH 5.0f

typedef unsigned long long u64;

// ---------- packed f32x2 helpers ----------
__device__ __forceinline__ u64 pk(float lo, float hi) {
    u64 r; asm("mov.b64 %0, {%1, %2};" : "=l"(r) : "f"(lo), "f"(hi)); return r;
}
__device__ __forceinline__ void upk(u64 v, float& lo, float& hi) {
    asm("mov.b64 {%0, %1}, %2;" : "=f"(lo), "=f"(hi) : "l"(v));
}
__device__ __forceinline__ u64 fma2(u64 a, u64 b, u64 c) {
    u64 d; asm("fma.rn.f32x2 %0, %1, %2, %3;" : "=l"(d) : "l"(a), "l"(b), "l"(c)); return d;
}
__device__ __forceinline__ u64 cos2(u64 v) {
    float lo, hi; upk(v, lo, hi);
    return pk(__cosf(lo), __cosf(hi));
}

// ---------- prelude results ----------
__device__ float g_A[4];                     // expm(gen)
__device__ __align__(8) float g_bns[32];     // gamma * rsqrt(var+eps)
__device__ __align__(8) float g_bno[32];     // beta - mean * scale

__global__ void prelude_kernel(const float* __restrict__ gen,
                               const float* __restrict__ gam,
                               const float* __restrict__ bet,
                               const float* __restrict__ mean,
                               const float* __restrict__ var) {
    int t = threadIdx.x;
    if (t == 0) {
        double m0 = gen[0], m1 = gen[1], m2 = gen[2], m3 = gen[3];
        double a0 = 1.0, a1 = 0.0, a2 = 0.0, a3 = 1.0;
        double t0 = 1.0, t1 = 0.0, t2 = 0.0, t3 = 1.0;
        for (int k = 1; k <= 18; k++) {
            double n0 = (t0 * m0 + t1 * m2) / k;
            double n1 = (t0 * m1 + t1 * m3) / k;
            double n2 = (t2 * m0 + t3 * m2) / k;
            double n3 = (t2 * m1 + t3 * m3) / k;
            t0 = n0; t1 = n1; t2 = n2; t3 = n3;
            a0 += n0; a1 += n1; a2 += n2; a3 += n3;
        }
        g_A[0] = (float)a0; g_A[1] = (float)a1;
        g_A[2] = (float)a2; g_A[3] = (float)a3;
    }
    if (t < 32) {
        float s = gam[t] * rsqrtf(var[t] + 0.001f);
        g_bns[t] = s;
        g_bno[t] = bet[t] - mean[t] * s;
    }
}

// ---------- bilinear sample ----------
__device__ __forceinline__ float bil(const float* __restrict__ img, float r, float c) {
    r = fminf(fmaxf(r, 0.0f), (float)(H - 1));
    c = fminf(fmaxf(c, 0.0f), (float)(H - 1));
    float rf = floorf(r), cf = floorf(c);
    int r0 = (int)rf, c0 = (int)cf;
    int r1 = min(r0 + 1, H - 1), c1 = min(c0 + 1, H - 1);
    float wr = r - rf, wc = c - cf;
    float v00 = __ldg(img + r0 * H + c0);
    float v01 = __ldg(img + r0 * H + c1);
    float v10 = __ldg(img + r1 * H + c0);
    float v11 = __ldg(img + r1 * H + c1);
    float top = v00 + wc * (v01 - v00);
    float bot = v10 + wc * (v11 - v10);
    return top + wr * (bot - top);
}

// ---------- main kernel ----------
// 2 pixels/thread. f32x2 lanes = two adjacent OUTPUT columns of one pixel.
// Weight operand: non-duplicated LDS.128 {w[k][4q..4q+3]} -> feeds 4 FFMA2
// (2 column-pairs x 2 pixels). Activation dup {y[k],y[k]} lives in regs and
// is reused across all 8 column-quads.
#define BLK 128
__global__ __launch_bounds__(BLK)
void rmodel_kernel(const float* __restrict__ x,
                   const float* __restrict__ trans,
                   const float* __restrict__ w0, const float* __restrict__ b0,
                   const float* __restrict__ w1, const float* __restrict__ b1,
                   const float* __restrict__ w2, const float* __restrict__ b2,
                   const float* __restrict__ wf,
                   const float* __restrict__ img,
                   float* __restrict__ out) {
    __shared__ ulonglong2 s_w1[256];   // [k*8+q] = cols 4q..4q+3 of row k
    __shared__ ulonglong2 s_w2[256];
    __shared__ ulonglong2 s_w0[16];    // [c*8+q]
    __shared__ u64 s_b0[16], s_b1[16], s_b2[16];
    __shared__ u64 s_bns[16], s_bno[16];
    __shared__ ulonglong2 s_wf[16];    // [k/2] = {wf[k][0..1], wf[k+1][0..1]}

    int tid = threadIdx.x;
    {   // rows are contiguous floats -> quads are direct 16B copies
        const ulonglong2* gw1 = (const ulonglong2*)w1;
        const ulonglong2* gw2 = (const ulonglong2*)w2;
        for (int e = tid; e < 256; e += BLK) { s_w1[e] = gw1[e]; s_w2[e] = gw2[e]; }
        if (tid < 16) {
            s_w0[tid] = ((const ulonglong2*)w0)[tid];
            s_wf[tid] = ((const ulonglong2*)wf)[tid];
            s_b0[tid]  = ((const u64*)b0)[tid];
            s_b1[tid]  = ((const u64*)b1)[tid];
            s_b2[tid]  = ((const u64*)b2)[tid];
            s_bns[tid] = pk(g_bns[2 * tid], g_bns[2 * tid + 1]);
            s_bno[tid] = pk(g_bno[2 * tid], g_bno[2 * tid + 1]);
        }
    }
    __syncthreads();

    int i = blockIdx.x * BLK + tid;           // pixels (i, i+HALF)
    int ib = i + HALF;

    float xa0 = __ldg(x + 3 * i),  xa1 = __ldg(x + 3 * i + 1);
    float xb0 = __ldg(x + 3 * ib), xb1 = __ldg(x + 3 * ib + 1);

    float A0 = g_A[0], A1 = g_A[1], A2 = g_A[2], A3 = g_A[3];
    float t0 = __ldg(trans), t1 = __ldg(trans + 1);

    // c = A x + t
    float ca0 = fmaf(A0, xa0, fmaf(A1, xa1, t0));
    float ca1 = fmaf(A2, xa0, fmaf(A3, xa1, t1));
    float cb0 = fmaf(A0, xb0, fmaf(A1, xb1, t0));
    float cb1 = fmaf(A2, xb0, fmaf(A3, xb1, t1));

    u64 accA[16], accB[16];
    float yA[32], yB[32];
    float zA[32], zB[32];

    // ---- layer 0: 2 -> 32 ----
    {
        u64 a0d = pk(ca0 * SCALE_INV, ca0 * SCALE_INV);
        u64 a1d = pk(ca1 * SCALE_INV, ca1 * SCALE_INV);
        u64 b0d = pk(cb0 * SCALE_INV, cb0 * SCALE_INV);
        u64 b1d = pk(cb1 * SCALE_INV, cb1 * SCALE_INV);
        #pragma unroll
        for (int q = 0; q < 8; q++) {
            ulonglong2 wa = s_w0[q], wb = s_w0[8 + q];
            u64 bias0 = s_b0[2 * q], bias1 = s_b0[2 * q + 1];
            u64 ra0 = fma2(a0d, wa.x, fma2(a1d, wb.x, bias0));
            u64 ra1 = fma2(a0d, wa.y, fma2(a1d, wb.y, bias1));
            u64 rb0 = fma2(b0d, wa.x, fma2(b1d, wb.x, bias0));
            u64 rb1 = fma2(b0d, wa.y, fma2(b1d, wb.y, bias1));
            float u, v;
            upk(ra0, u, v); yA[4 * q] = __cosf(u); yA[4 * q + 1] = __cosf(v);
            upk(ra1, u, v); yA[4 * q + 2] = __cosf(u); yA[4 * q + 3] = __cosf(v);
            upk(rb0, u, v); yB[4 * q] = __cosf(u); yB[4 * q + 1] = __cosf(v);
            upk(rb1, u, v); yB[4 * q + 2] = __cosf(u); yB[4 * q + 3] = __cosf(v);
        }
    }

    // ---- layer 1: 32 -> 32 ----
    #pragma unroll
    for (int jp = 0; jp < 16; jp++) { accA[jp] = s_b1[jp]; accB[jp] = s_b1[jp]; }
    #pragma unroll
    for (int k = 0; k < 32; k++) {
        u64 da = pk(yA[k], yA[k]);
        u64 db = pk(yB[k], yB[k]);
        #pragma unroll
        for (int q = 0; q < 8; q++) {
            ulonglong2 w = s_w1[k * 8 + q];
            accA[2 * q]     = fma2(da, w.x, accA[2 * q]);
            accA[2 * q + 1] = fma2(da, w.y, accA[2 * q + 1]);
            accB[2 * q]     = fma2(db, w.x, accB[2 * q]);
            accB[2 * q + 1] = fma2(db, w.y, accB[2 * q + 1]);
        }
    }
    #pragma unroll
    for (int jp = 0; jp < 16; jp++) {
        float u, v;
        upk(accA[jp], u, v); zA[2 * jp] = __cosf(u); zA[2 * jp + 1] = __cosf(v);
        upk(accB[jp], u, v); zB[2 * jp] = __cosf(u); zB[2 * jp + 1] = __cosf(v);
    }

    // ---- layer 2: 32 -> 32, fused BN + cos ----
    #pragma unroll
    for (int jp = 0; jp < 16; jp++) { accA[jp] = s_b2[jp]; accB[jp] = s_b2[jp]; }
    #pragma unroll
    for (int k = 0; k < 32; k++) {
        u64 da = pk(zA[k], zA[k]);
        u64 db = pk(zB[k], zB[k]);
        #pragma unroll
        for (int q = 0; q < 8; q++) {
            ulonglong2 w = s_w2[k * 8 + q];
            accA[2 * q]     = fma2(da, w.x, accA[2 * q]);
            accA[2 * q + 1] = fma2(da, w.y, accA[2 * q + 1]);
            accB[2 * q]     = fma2(db, w.x, accB[2 * q]);
            accB[2 * q + 1] = fma2(db, w.y, accB[2 * q + 1]);
        }
    }
    #pragma unroll
    for (int jp = 0; jp < 16; jp++) {
        u64 s = s_bns[jp], o = s_bno[jp];
        u64 qa = cos2(fma2(cos2(accA[jp]), s, o));
        u64 qb = cos2(fma2(cos2(accB[jp]), s, o));
        upk(qa, yA[2 * jp], yA[2 * jp + 1]);
        upk(qb, yB[2 * jp], yB[2 * jp + 1]);
    }

    // ---- final 32 -> 2 (packed {d_row, d_col}), c += 5*d ----
    u64 dA = 0ull, dB = 0ull;
    #pragma unroll
    for (int kp = 0; kp < 16; kp++) {
        ulonglong2 w = s_wf[kp];   // rows 2kp, 2kp+1
        dA = fma2(pk(yA[2 * kp], yA[2 * kp]), w.x, dA);
        dA = fma2(pk(yA[2 * kp + 1], yA[2 * kp + 1]), w.y, dA);
        dB = fma2(pk(yB[2 * kp], yB[2 * kp]), w.x, dB);
        dB = fma2(pk(yB[2 * kp + 1], yB[2 * kp + 1]), w.y, dB);
    }
    u64 five = pk(STRENGTH, STRENGTH);
    u64 cfA = fma2(five, dA, pk(ca0, ca1));
    u64 cfB = fma2(five, dB, pk(cb0, cb1));

    float ra, rca, rb, rcb;
    upk(cfA, ra, rca);
    upk(cfB, rb, rcb);

    out[i]  = bil(img, ra, rca);
    out[ib] = bil(img, rb, rcb);
}

extern "C" void kernel_launch(void* const* d_in, const int* in_sizes, int n_in,
                              void* d_out, int out_size) {
    const float* x      = (const float*)d_in[0];
    const float* gen    = (const float*)d_in[1];
    const float* trans  = (const float*)d_in[2];
    const float* w0     = (const float*)d_in[3];
    const float* b0     = (const float*)d_in[4];
    const float* w1     = (const float*)d_in[5];
    const float* b1     = (const float*)d_in[6];
    const float* w2     = (const float*)d_in[7];
    const float* b2     = (const float*)d_in[8];
    const float* gam    = (const float*)d_in[9];
    const float* bet    = (const float*)d_in[10];
    const float* mean   = (const float*)d_in[11];
    const float* var    = (const float*)d_in[12];
    const float* wf     = (const float*)d_in[13];
    const float* img    = (const float*)d_in[14];
    float* out = (float*)d_out;

    prelude_kernel<<<1, 32>>>(gen, gam, bet, mean, var);
    rmodel_kernel<<<HALF / BLK, BLK>>>(x, trans, w0, b0, w1, b1, w2, b2,
                                       wf, img, out);
}

// round 6
// speedup vs baseline: 1.7439x; 1.1863x over previous
#include <cuda_runtime.h>
#include <cstdint>

#define H 512
#define TOT (16*256*256)
#define HALF (TOT/2)
#define SCALE_INV 0.1f
#define STRENGTH 5.0f

typedef unsigned long long u64;

// ---------- packed f32x2 helpers ----------
__device__ __forceinline__ u64 pk(float lo, float hi) {
    u64 r; asm("mov.b64 %0, {%1, %2};" : "=l"(r) : "f"(lo), "f"(hi)); return r;
}
__device__ __forceinline__ void upk(u64 v, float& lo, float& hi) {
    asm("mov.b64 {%0, %1}, %2;" : "=f"(lo), "=f"(hi) : "l"(v));
}
__device__ __forceinline__ u64 fma2(u64 a, u64 b, u64 c) {
    u64 d; asm("fma.rn.f32x2 %0, %1, %2, %3;" : "=l"(d) : "l"(a), "l"(b), "l"(c)); return d;
}
__device__ __forceinline__ u64 cos2(u64 v) {
    float lo, hi; upk(v, lo, hi);
    return pk(__cosf(lo), __cosf(hi));
}

// ---------- prelude results ----------
__device__ float g_A[4];
__device__ __align__(8) float g_bns[32];
__device__ __align__(8) float g_bno[32];

__global__ void prelude_kernel(const float* __restrict__ gen,
                               const float* __restrict__ gam,
                               const float* __restrict__ bet,
                               const float* __restrict__ mean,
                               const float* __restrict__ var) {
    int t = threadIdx.x;
    if (t == 0) {
        double m0 = gen[0], m1 = gen[1], m2 = gen[2], m3 = gen[3];
        double a0 = 1.0, a1 = 0.0, a2 = 0.0, a3 = 1.0;
        double t0 = 1.0, t1 = 0.0, t2 = 0.0, t3 = 1.0;
        for (int k = 1; k <= 18; k++) {
            double n0 = (t0 * m0 + t1 * m2) / k;
            double n1 = (t0 * m1 + t1 * m3) / k;
            double n2 = (t2 * m0 + t3 * m2) / k;
            double n3 = (t2 * m1 + t3 * m3) / k;
            t0 = n0; t1 = n1; t2 = n2; t3 = n3;
            a0 += n0; a1 += n1; a2 += n2; a3 += n3;
        }
        g_A[0] = (float)a0; g_A[1] = (float)a1;
        g_A[2] = (float)a2; g_A[3] = (float)a3;
    }
    if (t < 32) {
        float s = gam[t] * rsqrtf(var[t] + 0.001f);
        g_bns[t] = s;
        g_bno[t] = bet[t] - mean[t] * s;
    }
}

// ---------- bilinear sample ----------
__device__ __forceinline__ float bil(const float* __restrict__ img, float r, float c) {
    r = fminf(fmaxf(r, 0.0f), (float)(H - 1));
    c = fminf(fmaxf(c, 0.0f), (float)(H - 1));
    float rf = floorf(r), cf = floorf(c);
    int r0 = (int)rf, c0 = (int)cf;
    int r1 = min(r0 + 1, H - 1), c1 = min(c0 + 1, H - 1);
    float wr = r - rf, wc = c - cf;
    float v00 = __ldg(img + r0 * H + c0);
    float v01 = __ldg(img + r0 * H + c1);
    float v10 = __ldg(img + r1 * H + c0);
    float v11 = __ldg(img + r1 * H + c1);
    float top = v00 + wc * (v01 - v00);
    float bot = v10 + wc * (v11 - v10);
    return top + wr * (bot - top);
}

// ---------- main kernel ----------
// 2 px/thread, f32x2 lanes = two adjacent OUTPUT columns.
// Register diet for 16 warps/SM:
//  - layer0 fused into layer1 k-loop (y computed on the fly, no y arrays)
//  - layer2 split in two column-halves (8 accs live), final projection
//    accumulated per half so finished activations die immediately.
#define BLK 128
__global__ __launch_bounds__(BLK, 4)
void rmodel_kernel(const float* __restrict__ x,
                   const float* __restrict__ trans,
                   const float* __restrict__ w0, const float* __restrict__ b0,
                   const float* __restrict__ w1, const float* __restrict__ b1,
                   const float* __restrict__ w2, const float* __restrict__ b2,
                   const float* __restrict__ wf,
                   const float* __restrict__ img,
                   float* __restrict__ out) {
    __shared__ ulonglong2 s_w1[256];   // [k*8+q] = w1 row k, cols 4q..4q+3
    __shared__ ulonglong2 s_w2[256];
    __shared__ ulonglong2 s_l0[32];    // [k]: .x = dup w0[0][k], .y = dup w0[1][k]
    __shared__ u64 s_l0b[32];          // dup b0[k]
    __shared__ u64 s_b1[16], s_b2[16];
    __shared__ u64 s_bns[16], s_bno[16];
    __shared__ ulonglong2 s_wf[16];    // [j] = {wf rows 2j, 2j+1}

    int tid = threadIdx.x;
    {
        const ulonglong2* gw1 = (const ulonglong2*)w1;
        const ulonglong2* gw2 = (const ulonglong2*)w2;
        for (int e = tid; e < 256; e += BLK) { s_w1[e] = gw1[e]; s_w2[e] = gw2[e]; }
        if (tid < 32) {
            float wa = w0[tid], wb = w0[32 + tid], bb = b0[tid];
            s_l0[tid] = make_ulonglong2(pk(wa, wa), pk(wb, wb));
            s_l0b[tid] = pk(bb, bb);
        }
        if (tid < 16) {
            s_wf[tid]  = ((const ulonglong2*)wf)[tid];
            s_b1[tid]  = ((const u64*)b1)[tid];
            s_b2[tid]  = ((const u64*)b2)[tid];
            s_bns[tid] = pk(g_bns[2 * tid], g_bns[2 * tid + 1]);
            s_bno[tid] = pk(g_bno[2 * tid], g_bno[2 * tid + 1]);
        }
    }
    __syncthreads();

    int i = blockIdx.x * BLK + tid;           // pixels (i, i+HALF)
    int ib = i + HALF;

    float xa0 = __ldg(x + 3 * i),  xa1 = __ldg(x + 3 * i + 1);
    float xb0 = __ldg(x + 3 * ib), xb1 = __ldg(x + 3 * ib + 1);

    float A0 = g_A[0], A1 = g_A[1], A2 = g_A[2], A3 = g_A[3];
    float t0 = __ldg(trans), t1 = __ldg(trans + 1);

    float ca0 = fmaf(A0, xa0, fmaf(A1, xa1, t0));
    float ca1 = fmaf(A2, xa0, fmaf(A3, xa1, t1));
    float cb0 = fmaf(A0, xb0, fmaf(A1, xb1, t0));
    float cb1 = fmaf(A2, xb0, fmaf(A3, xb1, t1));

    // lanes of pa* = pixels {A, B}
    u64 pa0 = pk(ca0 * SCALE_INV, cb0 * SCALE_INV);
    u64 pa1 = pk(ca1 * SCALE_INV, cb1 * SCALE_INV);

    // ---- layer 1 (layer 0 fused into k-loop) ----
    u64 accA[16], accB[16];
    #pragma unroll
    for (int jp = 0; jp < 16; jp++) { u64 b = s_b1[jp]; accA[jp] = b; accB[jp] = b; }

    #pragma unroll 4
    for (int k = 0; k < 32; k++) {
        ulonglong2 w0k = s_l0[k];
        u64 arg = fma2(pa0, w0k.x, fma2(pa1, w0k.y, s_l0b[k]));
        float uA, uB; upk(arg, uA, uB);
        float ykA = __cosf(uA), ykB = __cosf(uB);
        u64 da = pk(ykA, ykA), db = pk(ykB, ykB);
        #pragma unroll
        for (int q = 0; q < 8; q++) {
            ulonglong2 w = s_w1[k * 8 + q];
            accA[2 * q]     = fma2(da, w.x, accA[2 * q]);
            accA[2 * q + 1] = fma2(da, w.y, accA[2 * q + 1]);
            accB[2 * q]     = fma2(db, w.x, accB[2 * q]);
            accB[2 * q + 1] = fma2(db, w.y, accB[2 * q + 1]);
        }
    }

    // z = cos(acc), stored as f32 (acc regs freed after this)
    float zA[32], zB[32];
    #pragma unroll
    for (int jp = 0; jp < 16; jp++) {
        float u, v;
        upk(accA[jp], u, v); zA[2 * jp] = __cosf(u); zA[2 * jp + 1] = __cosf(v);
        upk(accB[jp], u, v); zB[2 * jp] = __cosf(u); zB[2 * jp + 1] = __cosf(v);
    }

    // ---- layer 2 in two column-halves + fused BN/cos + partial wf proj ----
    u64 dA = 0ull, dB = 0ull;
    #pragma unroll
    for (int h = 0; h < 2; h++) {
        u64 a2A[8], a2B[8];
        #pragma unroll
        for (int jp = 0; jp < 8; jp++) { u64 b = s_b2[8 * h + jp]; a2A[jp] = b; a2B[jp] = b; }
        #pragma unroll
        for (int k = 0; k < 32; k++) {
            u64 da = pk(zA[k], zA[k]);
            u64 db = pk(zB[k], zB[k]);
            #pragma unroll
            for (int q = 0; q < 4; q++) {
                ulonglong2 w = s_w2[k * 8 + 4 * h + q];
                a2A[2 * q]     = fma2(da, w.x, a2A[2 * q]);
                a2A[2 * q + 1] = fma2(da, w.y, a2A[2 * q + 1]);
                a2B[2 * q]     = fma2(db, w.x, a2B[2 * q]);
                a2B[2 * q + 1] = fma2(db, w.y, a2B[2 * q + 1]);
            }
        }
        #pragma unroll
        for (int jp = 0; jp < 8; jp++) {
            int j = 8 * h + jp;                 // global column-pair
            u64 s = s_bns[j], o = s_bno[j];
            ulonglong2 wfp = s_wf[j];           // wf rows 2j, 2j+1
            u64 qa = cos2(fma2(cos2(a2A[jp]), s, o));
            u64 qb = cos2(fma2(cos2(a2B[jp]), s, o));
            float f0, f1;
            upk(qa, f0, f1);
            dA = fma2(pk(f0, f0), wfp.x, dA);
            dA = fma2(pk(f1, f1), wfp.y, dA);
            upk(qb, f0, f1);
            dB = fma2(pk(f0, f0), wfp.x, dB);
            dB = fma2(pk(f1, f1), wfp.y, dB);
        }
    }

    u64 five = pk(STRENGTH, STRENGTH);
    u64 cfA = fma2(five, dA, pk(ca0, ca1));
    u64 cfB = fma2(five, dB, pk(cb0, cb1));

    float ra, rca, rb, rcb;
    upk(cfA, ra, rca);
    upk(cfB, rb, rcb);

    out[i]  = bil(img, ra, rca);
    out[ib] = bil(img, rb, rcb);
}

extern "C" void kernel_launch(void* const* d_in, const int* in_sizes, int n_in,
                              void* d_out, int out_size) {
    const float* x      = (const float*)d_in[0];
    const float* gen    = (const float*)d_in[1];
    const float* trans  = (const float*)d_in[2];
    const float* w0     = (const float*)d_in[3];
    const float* b0     = (const float*)d_in[4];
    const float* w1     = (const float*)d_in[5];
    const float* b1     = (const float*)d_in[6];
    const float* w2     = (const float*)d_in[7];
    const float* b2     = (const float*)d_in[8];
    const float* gam    = (const float*)d_in[9];
    const float* bet    = (const float*)d_in[10];
    const float* mean   = (const float*)d_in[11];
    const float* var    = (const float*)d_in[12];
    const float* wf     = (const float*)d_in[13];
    const float* img    = (const float*)d_in[14];
    float* out = (float*)d_out;

    prelude_kernel<<<1, 32>>>(gen, gam, bet, mean, var);
    rmodel_kernel<<<HALF / BLK, BLK>>>(x, trans, w0, b0, w1, b1, w2, b2,
                                       wf, img, out);
}